// round 9
// baseline (speedup 1.0000x reference)
#include <cuda_runtime.h>
#include <cuda_fp16.h>
#include <cstdint>

#define B_SZ   4096
#define IN_SZ  1024
#define HID_SZ 2048
#define D_SZ   3072
#define FOURH  8192
#define BK     64
#define NTILES (D_SZ / BK)   // 48

#define TM 128               // CTA M tile
#define TN 256               // CTA N tile (= 64 hidden cols x 4 gates, interleaved)
#define STAGES 4
#define A_BYTES (TM * BK * 2)          // 16384
#define B_BYTES (TN * BK * 2)          // 32768
#define STAGE_BYTES (A_BYTES + B_BYTES) // 49152
#define SMEM_BYTES (STAGES * STAGE_BYTES)  // 196608

// -------- scratch (device globals; no allocation allowed) --------
__device__ __half g_A[(size_t)B_SZ * D_SZ];    // [4096, 3072] combined, fp16
__device__ __half g_W[(size_t)FOURH * D_SZ];   // permuted weights, fp16

// ======================= helpers =======================
__device__ __forceinline__ uint32_t smem_u32(const void* p) {
    uint32_t a;
    asm("{ .reg .u64 t; cvta.to.shared.u64 t, %1; cvt.u32.u64 %0, t; }"
        : "=r"(a) : "l"(p));
    return a;
}

__device__ __forceinline__ void cp16(uint32_t dst, const void* src) {
    asm volatile("cp.async.cg.shared.global [%0], [%1], 16;"
                 :: "r"(dst), "l"(__cvta_generic_to_global(src)));
}
#define CP_COMMIT() asm volatile("cp.async.commit_group;")

__device__ __forceinline__ void ldx4(uint32_t& r0, uint32_t& r1, uint32_t& r2,
                                     uint32_t& r3, uint32_t addr) {
    asm volatile("ldmatrix.sync.aligned.m8n8.x4.shared.b16 {%0,%1,%2,%3}, [%4];"
                 : "=r"(r0), "=r"(r1), "=r"(r2), "=r"(r3) : "r"(addr));
}

__device__ __forceinline__ void mma16816(float* c, const uint32_t* a,
                                         const uint32_t* b) {
    asm volatile(
        "mma.sync.aligned.m16n8k16.row.col.f32.f16.f16.f32 "
        "{%0,%1,%2,%3}, {%4,%5,%6,%7}, {%8,%9}, {%0,%1,%2,%3};"
        : "+f"(c[0]), "+f"(c[1]), "+f"(c[2]), "+f"(c[3])
        : "r"(a[0]), "r"(a[1]), "r"(a[2]), "r"(a[3]), "r"(b[0]), "r"(b[1]));
}

__device__ __forceinline__ float tanh_ap(float x) {
    float y;
    asm("tanh.approx.f32 %0, %1;" : "=f"(y) : "f"(x));
    return y;
}
__device__ __forceinline__ float sigf(float x) {
    return 0.5f * tanh_ap(0.5f * x) + 0.5f;
}

// ======================= merged conversion kernel =======================
#define A_UNITS ((size_t)B_SZ * D_SZ / 4)    // 3145728
#define W_UNITS ((size_t)FOURH * D_SZ / 4)   // 6291456
#define A_BLK ((unsigned)(A_UNITS / 256))    // 12288
#define W_BLK ((unsigned)(W_UNITS / 256))    // 24576

__global__ void __launch_bounds__(256)
conv_all_kernel(const float* __restrict__ x, const float* __restrict__ h,
                const float* __restrict__ Wi, const float* __restrict__ Wf,
                const float* __restrict__ Wc, const float* __restrict__ Wo)
{
    const unsigned bid = blockIdx.x;
    if (bid < A_BLK) {
        size_t e = ((size_t)bid * 256 + threadIdx.x) * 4;
        int r = (int)(e / D_SZ), k = (int)(e % D_SZ);
        float4 v = (k < IN_SZ)
            ? *reinterpret_cast<const float4*>(x + (size_t)r * IN_SZ + k)
            : *reinterpret_cast<const float4*>(h + (size_t)r * HID_SZ + (k - IN_SZ));
        __half2 lo = __floats2half2_rn(v.x, v.y);
        __half2 hi = __floats2half2_rn(v.z, v.w);
        uint2 pk;
        pk.x = *reinterpret_cast<uint32_t*>(&lo);
        pk.y = *reinterpret_cast<uint32_t*>(&hi);
        *reinterpret_cast<uint2*>(g_A + e) = pk;
    } else {
        // Warp tile is 32 N-cols = 4 gates x 8 hidden cols.
        // g_W row R = nb*256 + n:  nw = n>>5 (warp col), w32 = n&31,
        // gate g = w32>>3, rr = w32&7, source row = W_g[nb*64 + nw*8 + rr].
        // Thread (lane&3)=l then owns cols rr = 2l,2l+1 for every gate.
        size_t e = ((size_t)(bid - A_BLK) * 256 + threadIdx.x) * 4;
        int row = (int)(e / D_SZ), k = (int)(e % D_SZ);
        int nb = row >> 8, n = row & 255;
        int nw = n >> 5, w32 = n & 31;
        int g = w32 >> 3, rr = w32 & 7;
        int hr = nb * 64 + nw * 8 + rr;
        const float* W = (g == 0) ? Wi : (g == 1) ? Wf : (g == 2) ? Wc : Wo;
        float4 v = *reinterpret_cast<const float4*>(W + (size_t)hr * D_SZ + k);
        __half2 lo = __floats2half2_rn(v.x, v.y);
        __half2 hi = __floats2half2_rn(v.z, v.w);
        uint2 pk;
        pk.x = *reinterpret_cast<uint32_t*>(&lo);
        pk.y = *reinterpret_cast<uint32_t*>(&hi);
        *reinterpret_cast<uint2*>(g_W + e) = pk;
    }
}

// ======================= main fused GEMM + LSTM epilogue =======================
// 512 threads: warp grid 2 (M) x 8 (N), warp tile 64x32.
__global__ void __launch_bounds__(512, 1)
lstm_gemm_kernel(const float* __restrict__ c_prev,
                 const float* __restrict__ b_i, const float* __restrict__ b_f,
                 const float* __restrict__ b_c, const float* __restrict__ b_o,
                 float* __restrict__ out)
{
    extern __shared__ __align__(128) char smem[];
    const uint32_t sb = smem_u32(smem);
    const int tid = threadIdx.x;
    const int wid = tid >> 5, lane = tid & 31;
    const int wm = wid >> 3;            // 0..1  (M warp, 64 rows)
    const int wn = wid & 7;             // 0..7  (N warp, 32 cols)
    const int nb = blockIdx.x;          // 0..31 : block of 64 hidden cols
    const int m0 = blockIdx.y << 7;     // 0..31 : block of 128 batch rows

    const __half* gA = g_A + (size_t)m0 * D_SZ;
    const __half* gB = g_W + (size_t)nb * TN * D_SZ;

    // ---- cp.async tile loader (512 threads: 64 rows x 8 chunks per pass) ----
    const int ldrow = tid >> 3;   // 0..63
    const int ldch  = tid & 7;    // 16B chunk
    auto load_stage = [&](int s, int kt) {
        uint32_t base = sb + (uint32_t)s * STAGE_BYTES;
        const __half* srcA = gA + (size_t)ldrow * D_SZ + kt * BK + ldch * 8;
        const __half* srcB = gB + (size_t)ldrow * D_SZ + kt * BK + ldch * 8;
        uint32_t so = (uint32_t)(ldrow << 7) + ((uint32_t)(ldch << 4) ^ (((uint32_t)ldrow & 7) << 4));
#pragma unroll
        for (int i = 0; i < 2; i++)   // A: 128 rows
            cp16(base + so + (uint32_t)(i << 13), srcA + (size_t)(i * 64) * D_SZ);
#pragma unroll
        for (int i = 0; i < 4; i++)   // B: 256 rows
            cp16(base + A_BYTES + so + (uint32_t)(i << 13), srcB + (size_t)(i * 64) * D_SZ);
    };

    // ---- ldmatrix addressing ----
    const int laneRow = lane & 15;
    const uint32_t laneK = (uint32_t)(lane >> 4) << 4;     // 0 or 16 bytes
    const uint32_t swzm = ((uint32_t)laneRow & 7) << 4;    // SW128 xor mask
    uint32_t rowA[4], rowB[2];
#pragma unroll
    for (int f = 0; f < 4; f++)
        rowA[f] = (uint32_t)((wm * 64 + f * 16 + laneRow) << 7);
#pragma unroll
    for (int f = 0; f < 2; f++)
        rowB[f] = (uint32_t)((wn * 32 + f * 16 + laneRow) << 7) + A_BYTES;

    float acc[4][4][4];
#pragma unroll
    for (int i = 0; i < 4; i++)
#pragma unroll
        for (int j = 0; j < 4; j++)
#pragma unroll
            for (int r = 0; r < 4; r++) acc[i][j][r] = 0.f;

    // ---- pipeline: 4 stages, prefetch distance 3 ----
    load_stage(0, 0); CP_COMMIT();
    load_stage(1, 1); CP_COMMIT();
    load_stage(2, 2); CP_COMMIT();

#pragma unroll 1
    for (int t = 0; t < NTILES; t++) {
        if (t >= NTILES - 3) asm volatile("cp.async.wait_group 0;" ::: "memory");
        else                 asm volatile("cp.async.wait_group 2;" ::: "memory");
        __syncthreads();

        if (t + 3 < NTILES) {
            load_stage((t + 3) % STAGES, t + 3);
            CP_COMMIT();
        }

        const uint32_t stage = sb + (uint32_t)(t % STAGES) * STAGE_BYTES;
#pragma unroll
        for (int ks = 0; ks < 4; ks++) {
            const uint32_t colx = ((uint32_t)ks << 5) | laneK;
            uint32_t a[4][4], bf[4][2];
#pragma unroll
            for (int mf = 0; mf < 4; mf++)
                ldx4(a[mf][0], a[mf][1], a[mf][2], a[mf][3],
                     stage + rowA[mf] + (colx ^ swzm));
#pragma unroll
            for (int f = 0; f < 2; f++) {
                uint32_t r0, r1, r2, r3;
                ldx4(r0, r1, r2, r3, stage + rowB[f] + (colx ^ swzm));
                bf[2 * f][0] = r0; bf[2 * f][1] = r2;
                bf[2 * f + 1][0] = r1; bf[2 * f + 1][1] = r3;
            }
#pragma unroll
            for (int mf = 0; mf < 4; mf++)
#pragma unroll
                for (int nf = 0; nf < 4; nf++)
                    mma16816(acc[mf][nf], a[mf], bf[nf]);
        }
    }

    // ---- fused LSTM epilogue (all in registers) ----
    // nf indexes the gate (i,f,c,o); thread owns hidden cols hcg, hcg+1.
    const int l = lane & 3;
    const int hcg = nb * 64 + wn * 8 + 2 * l;
    const float2 bi2 = *reinterpret_cast<const float2*>(b_i + hcg);
    const float2 bf2 = *reinterpret_cast<const float2*>(b_f + hcg);
    const float2 bc2 = *reinterpret_cast<const float2*>(b_c + hcg);
    const float2 bo2 = *reinterpret_cast<const float2*>(b_o + hcg);
    const float bi_[2] = {bi2.x, bi2.y};
    const float bf_[2] = {bf2.x, bf2.y};
    const float bc_[2] = {bc2.x, bc2.y};
    const float bo_[2] = {bo2.x, bo2.y};

#pragma unroll
    for (int mf = 0; mf < 4; mf++) {
#pragma unroll
        for (int rh = 0; rh < 2; rh++) {
            const int m = m0 + wm * 64 + mf * 16 + (lane >> 2) + rh * 8;
            const float2 cp2 = *reinterpret_cast<const float2*>(
                c_prev + (size_t)m * HID_SZ + hcg);
            const float cpv[2] = {cp2.x, cp2.y};
            float hv[2], cv[2];
#pragma unroll
            for (int p = 0; p < 2; p++) {
                const int ci = rh * 2 + p;
                float gi = acc[mf][0][ci] + bi_[p];
                float gf = acc[mf][1][ci] + bf_[p];
                float gc = acc[mf][2][ci] + bc_[p];
                float go = acc[mf][3][ci] + bo_[p];
                float it = sigf(gi);
                float ft = sigf(gf);
                float gt = tanh_ap(gc);
                float ot = sigf(go);
                float ct = ft * cpv[p] + it * gt;
                cv[p] = ct;
                hv[p] = ot * tanh_ap(ct);
            }
            float2 h2 = {hv[0], hv[1]};
            float2 c2 = {cv[0], cv[1]};
            *reinterpret_cast<float2*>(out + (size_t)m * HID_SZ + hcg) = h2;
            *reinterpret_cast<float2*>(out + (size_t)B_SZ * HID_SZ +
                                       (size_t)m * HID_SZ + hcg) = c2;
        }
    }
}

// ======================= launcher =======================
extern "C" void kernel_launch(void* const* d_in, const int* in_sizes, int n_in,
                              void* d_out, int out_size) {
    const float* x  = (const float*)d_in[0];
    const float* h  = (const float*)d_in[1];
    const float* c  = (const float*)d_in[2];
    const float* Wi = (const float*)d_in[3];
    const float* bi = (const float*)d_in[4];
    const float* Wf = (const float*)d_in[5];
    const float* bf = (const float*)d_in[6];
    const float* Wc = (const float*)d_in[7];
    const float* bc = (const float*)d_in[8];
    const float* Wo = (const float*)d_in[9];
    const float* bo = (const float*)d_in[10];
    float* out = (float*)d_out;

    cudaFuncSetAttribute(lstm_gemm_kernel,
                         cudaFuncAttributeMaxDynamicSharedMemorySize, SMEM_BYTES);

    conv_all_kernel<<<A_BLK + W_BLK, 256>>>(x, h, Wi, Wf, Wc, Wo);
    lstm_gemm_kernel<<<dim3(HID_SZ / 64, B_SZ / TM), 512, SMEM_BYTES>>>(
        c, bi, bf, bc, bo, out);
}

// round 11
// speedup vs baseline: 1.0411x; 1.0411x over previous
#include <cuda_runtime.h>
#include <cuda_fp16.h>
#include <cstdint>

#define B_SZ   4096
#define IN_SZ  1024
#define HID_SZ 2048
#define D_SZ   3072
#define FOURH  8192
#define BK     64
#define NTILES (D_SZ / BK)   // 48

#define TM 128               // CTA M tile
#define TN 256               // CTA N tile (= 64 hidden cols x 4 gates, interleaved)
#define STAGES 4
#define A_BYTES (TM * BK * 2)          // 16384
#define B_BYTES (TN * BK * 2)          // 32768
#define STAGE_BYTES (A_BYTES + B_BYTES) // 49152
#define SMEM_BYTES (STAGES * STAGE_BYTES)  // 196608

// -------- scratch (device globals; no allocation allowed) --------
__device__ __half g_A[(size_t)B_SZ * D_SZ];    // [4096, 3072] combined, fp16
__device__ __half g_W[(size_t)FOURH * D_SZ];   // permuted weights, fp16

// ======================= helpers =======================
__device__ __forceinline__ uint32_t smem_u32(const void* p) {
    uint32_t a;
    asm("{ .reg .u64 t; cvta.to.shared.u64 t, %1; cvt.u32.u64 %0, t; }"
        : "=r"(a) : "l"(p));
    return a;
}

__device__ __forceinline__ void cp16(uint32_t dst, const void* src) {
    asm volatile("cp.async.cg.shared.global [%0], [%1], 16;"
                 :: "r"(dst), "l"(__cvta_generic_to_global(src)));
}
#define CP_COMMIT() asm volatile("cp.async.commit_group;")

__device__ __forceinline__ void ldx4(uint32_t& r0, uint32_t& r1, uint32_t& r2,
                                     uint32_t& r3, uint32_t addr) {
    asm volatile("ldmatrix.sync.aligned.m8n8.x4.shared.b16 {%0,%1,%2,%3}, [%4];"
                 : "=r"(r0), "=r"(r1), "=r"(r2), "=r"(r3) : "r"(addr));
}

__device__ __forceinline__ void mma16816(float* c, const uint32_t* a,
                                         const uint32_t* b) {
    asm volatile(
        "mma.sync.aligned.m16n8k16.row.col.f32.f16.f16.f32 "
        "{%0,%1,%2,%3}, {%4,%5,%6,%7}, {%8,%9}, {%0,%1,%2,%3};"
        : "+f"(c[0]), "+f"(c[1]), "+f"(c[2]), "+f"(c[3])
        : "r"(a[0]), "r"(a[1]), "r"(a[2]), "r"(a[3]), "r"(b[0]), "r"(b[1]));
}

__device__ __forceinline__ float tanh_ap(float x) {
    float y;
    asm("tanh.approx.f32 %0, %1;" : "=f"(y) : "f"(x));
    return y;
}
__device__ __forceinline__ float sigf(float x) {
    return 0.5f * tanh_ap(0.5f * x) + 0.5f;
}

// ======================= merged conversion kernel =======================
#define A_UNITS ((size_t)B_SZ * D_SZ / 4)    // 3145728
#define W_UNITS ((size_t)FOURH * D_SZ / 4)   // 6291456
#define A_BLK ((unsigned)(A_UNITS / 256))    // 12288
#define W_BLK ((unsigned)(W_UNITS / 256))    // 24576

__global__ void __launch_bounds__(256)
conv_all_kernel(const float* __restrict__ x, const float* __restrict__ h,
                const float* __restrict__ Wi, const float* __restrict__ Wf,
                const float* __restrict__ Wc, const float* __restrict__ Wo)
{
    const unsigned bid = blockIdx.x;
    if (bid < A_BLK) {
        size_t e = ((size_t)bid * 256 + threadIdx.x) * 4;
        int r = (int)(e / D_SZ), k = (int)(e % D_SZ);
        float4 v = (k < IN_SZ)
            ? *reinterpret_cast<const float4*>(x + (size_t)r * IN_SZ + k)
            : *reinterpret_cast<const float4*>(h + (size_t)r * HID_SZ + (k - IN_SZ));
        __half2 lo = __floats2half2_rn(v.x, v.y);
        __half2 hi = __floats2half2_rn(v.z, v.w);
        uint2 pk;
        pk.x = *reinterpret_cast<uint32_t*>(&lo);
        pk.y = *reinterpret_cast<uint32_t*>(&hi);
        *reinterpret_cast<uint2*>(g_A + e) = pk;
    } else {
        // Permute so one thread's accumulators hold all 4 gates of 4
        // consecutive hidden columns (64-wide warp N tile).
        size_t e = ((size_t)(bid - A_BLK) * 256 + threadIdx.x) * 4;
        int row = (int)(e / D_SZ), k = (int)(e % D_SZ);
        int nb = row >> 8, n = row & 255;
        int wn = n >> 6, n64 = n & 63;
        int nf = n64 >> 3, rr = n64 & 7;
        int l = rr >> 1, p = rr & 1;
        int g = nf >> 1;
        int hh = ((nf & 1) << 1) | p;
        int hc = wn * 16 + l * 4 + hh;
        int hr = nb * 64 + hc;
        const float* W = (g == 0) ? Wi : (g == 1) ? Wf : (g == 2) ? Wc : Wo;
        float4 v = *reinterpret_cast<const float4*>(W + (size_t)hr * D_SZ + k);
        __half2 lo = __floats2half2_rn(v.x, v.y);
        __half2 hi = __floats2half2_rn(v.z, v.w);
        uint2 pk;
        pk.x = *reinterpret_cast<uint32_t*>(&lo);
        pk.y = *reinterpret_cast<uint32_t*>(&hi);
        *reinterpret_cast<uint2*>(g_W + e) = pk;
    }
}

// ======================= main fused GEMM + LSTM epilogue =======================
// 256 threads: warp grid 2 (M) x 4 (N), warp tile 64x64.
// Fragment double-buffering: LDSM for ks+1 issued before MMAs of ks.
__global__ void __launch_bounds__(256, 1)
lstm_gemm_kernel(const float* __restrict__ c_prev,
                 const float* __restrict__ b_i, const float* __restrict__ b_f,
                 const float* __restrict__ b_c, const float* __restrict__ b_o,
                 float* __restrict__ out)
{
    extern __shared__ __align__(128) char smem[];
    const uint32_t sb = smem_u32(smem);
    const int tid = threadIdx.x;
    const int wid = tid >> 5, lane = tid & 31;
    const int wm = wid >> 2;            // 0..1  (M warp, 64 rows)
    const int wn = wid & 3;             // 0..3  (N warp, 64 cols)
    const int nb = blockIdx.x;          // 0..31 : block of 64 hidden cols
    const int m0 = blockIdx.y << 7;     // 0..31 : block of 128 batch rows

    const __half* gA = g_A + (size_t)m0 * D_SZ;
    const __half* gB = g_W + (size_t)nb * TN * D_SZ;

    // ---- cp.async tile loader ----
    const int ldrow = tid >> 3;   // 0..31
    const int ldch  = tid & 7;    // 16B chunk
    auto load_stage = [&](int s, int kt) {
        uint32_t base = sb + (uint32_t)s * STAGE_BYTES;
        const __half* srcA = gA + (size_t)ldrow * D_SZ + kt * BK + ldch * 8;
        const __half* srcB = gB + (size_t)ldrow * D_SZ + kt * BK + ldch * 8;
        uint32_t so = (uint32_t)(ldrow << 7) + ((uint32_t)(ldch << 4) ^ (((uint32_t)ldrow & 7) << 4));
#pragma unroll
        for (int i = 0; i < 4; i++)   // A: 128 rows
            cp16(base + so + (uint32_t)(i << 12), srcA + (size_t)(i * 32) * D_SZ);
#pragma unroll
        for (int i = 0; i < 8; i++)   // B: 256 rows
            cp16(base + A_BYTES + so + (uint32_t)(i << 12), srcB + (size_t)(i * 32) * D_SZ);
    };

    // ---- ldmatrix addressing (per-thread constants) ----
    const int laneRow = lane & 15;
    const uint32_t laneK = (uint32_t)(lane >> 4) << 4;     // 0 or 16 bytes
    const uint32_t swzm = ((uint32_t)laneRow & 7) << 4;    // SW128 xor mask
    uint32_t rowA[4], rowB[4];
#pragma unroll
    for (int f = 0; f < 4; f++) {
        rowA[f] = (uint32_t)((wm * 64 + f * 16 + laneRow) << 7);
        rowB[f] = (uint32_t)((wn * 64 + f * 16 + laneRow) << 7) + A_BYTES;
    }
    uint32_t colxs[4];
#pragma unroll
    for (int ks = 0; ks < 4; ks++)
        colxs[ks] = (((uint32_t)ks << 5) | laneK) ^ swzm;

    float acc[4][8][4];
#pragma unroll
    for (int i = 0; i < 4; i++)
#pragma unroll
        for (int j = 0; j < 8; j++)
#pragma unroll
            for (int r = 0; r < 4; r++) acc[i][j][r] = 0.f;

    // double-buffered fragments
    uint32_t a[2][4][4], bfr[2][8][2];

    auto load_frags = [&](int buf, uint32_t stage, uint32_t colx) {
#pragma unroll
        for (int mf = 0; mf < 4; mf++)
            ldx4(a[buf][mf][0], a[buf][mf][1], a[buf][mf][2], a[buf][mf][3],
                 stage + rowA[mf] + colx);
#pragma unroll
        for (int np = 0; np < 4; np++) {
            uint32_t r0, r1, r2, r3;
            ldx4(r0, r1, r2, r3, stage + rowB[np] + colx);
            bfr[buf][2 * np][0] = r0;     bfr[buf][2 * np][1] = r2;
            bfr[buf][2 * np + 1][0] = r1; bfr[buf][2 * np + 1][1] = r3;
        }
    };

    // ---- pipeline: 4 smem stages, prefetch distance 3 ----
    load_stage(0, 0); CP_COMMIT();
    load_stage(1, 1); CP_COMMIT();
    load_stage(2, 2); CP_COMMIT();

#pragma unroll 1
    for (int t = 0; t < NTILES; t++) {
        if (t >= NTILES - 3) asm volatile("cp.async.wait_group 0;" ::: "memory");
        else                 asm volatile("cp.async.wait_group 2;" ::: "memory");
        __syncthreads();

        if (t + 3 < NTILES) {
            load_stage((t + 3) % STAGES, t + 3);
            CP_COMMIT();
        }

        const uint32_t stage = sb + (uint32_t)(t % STAGES) * STAGE_BYTES;
        load_frags(0, stage, colxs[0]);     // ks=0 fragments
#pragma unroll
        for (int ks = 0; ks < 4; ks++) {
            const int cur = ks & 1;
            if (ks < 3)                      // prefetch ks+1 before MMAs of ks
                load_frags(cur ^ 1, stage, colxs[ks + 1]);
#pragma unroll
            for (int mf = 0; mf < 4; mf++)
#pragma unroll
                for (int nf = 0; nf < 8; nf++)
                    mma16816(acc[mf][nf], a[cur][mf], bfr[cur][nf]);
        }
    }

    // ---- fused LSTM epilogue (all in registers) ----
    const int l = lane & 3;
    const int hcg = nb * 64 + wn * 16 + l * 4;   // 4 consecutive hidden cols
    const float4 bi4 = *reinterpret_cast<const float4*>(b_i + hcg);
    const float4 bf4 = *reinterpret_cast<const float4*>(b_f + hcg);
    const float4 bc4 = *reinterpret_cast<const float4*>(b_c + hcg);
    const float4 bo4 = *reinterpret_cast<const float4*>(b_o + hcg);
    const float bi_[4] = {bi4.x, bi4.y, bi4.z, bi4.w};
    const float bf_[4] = {bf4.x, bf4.y, bf4.z, bf4.w};
    const float bc_[4] = {bc4.x, bc4.y, bc4.z, bc4.w};
    const float bo_[4] = {bo4.x, bo4.y, bo4.z, bo4.w};

#pragma unroll
    for (int mf = 0; mf < 4; mf++) {
#pragma unroll
        for (int rh = 0; rh < 2; rh++) {
            const int m = m0 + wm * 64 + mf * 16 + (lane >> 2) + rh * 8;
            const float4 cp4 = *reinterpret_cast<const float4*>(
                c_prev + (size_t)m * HID_SZ + hcg);
            const float cpv[4] = {cp4.x, cp4.y, cp4.z, cp4.w};
            float hv[4], cv[4];
#pragma unroll
            for (int hh = 0; hh < 4; hh++) {
                const int nfo = hh >> 1;
                const int ci = rh * 2 + (hh & 1);
                float gi = acc[mf][0 + nfo][ci] + bi_[hh];
                float gf = acc[mf][2 + nfo][ci] + bf_[hh];
                float gc = acc[mf][4 + nfo][ci] + bc_[hh];
                float go = acc[mf][6 + nfo][ci] + bo_[hh];
                float it = sigf(gi);
                float ft = sigf(gf);
                float gt = tanh_ap(gc);
                float ot = sigf(go);
                float ct = ft * cpv[hh] + it * gt;
                cv[hh] = ct;
                hv[hh] = ot * tanh_ap(ct);
            }
            float4 h4 = {hv[0], hv[1], hv[2], hv[3]};
            float4 c4 = {cv[0], cv[1], cv[2], cv[3]};
            *reinterpret_cast<float4*>(out + (size_t)m * HID_SZ + hcg) = h4;
            *reinterpret_cast<float4*>(out + (size_t)B_SZ * HID_SZ +
                                       (size_t)m * HID_SZ + hcg) = c4;
        }
    }
}

// ======================= launcher =======================
extern "C" void kernel_launch(void* const* d_in, const int* in_sizes, int n_in,
                              void* d_out, int out_size) {
    const float* x  = (const float*)d_in[0];
    const float* h  = (const float*)d_in[1];
    const float* c  = (const float*)d_in[2];
    const float* Wi = (const float*)d_in[3];
    const float* bi = (const float*)d_in[4];
    const float* Wf = (const float*)d_in[5];
    const float* bf = (const float*)d_in[6];
    const float* Wc = (const float*)d_in[7];
    const float* bc = (const float*)d_in[8];
    const float* Wo = (const float*)d_in[9];
    const float* bo = (const float*)d_in[10];
    float* out = (float*)d_out;

    cudaFuncSetAttribute(lstm_gemm_kernel,
                         cudaFuncAttributeMaxDynamicSharedMemorySize, SMEM_BYTES);

    conv_all_kernel<<<A_BLK + W_BLK, 256>>>(x, h, Wi, Wf, Wc, Wo);
    lstm_gemm_kernel<<<dim3(HID_SZ / 64, B_SZ / TM), 256, SMEM_BYTES>>>(
        c, bi, bf, bc, bo, out);
}

// round 14
// speedup vs baseline: 1.0437x; 1.0025x over previous
#include <cuda_runtime.h>
#include <cuda_fp16.h>
#include <cstdint>

#define B_SZ   4096
#define IN_SZ  1024
#define HID_SZ 2048
#define D_SZ   3072
#define FOURH  8192
#define BK     64
#define NTILES (D_SZ / BK)   // 48
#define NSTREAM (NTILES * 4) // 192 k16 steps

#define TM 128               // CTA M tile
#define TN 256               // CTA N tile
#define STAGES 4
#define A_BYTES (TM * BK * 2)          // 16384 (A only in smem now)
#define STAGE_BYTES A_BYTES
#define SMEM_BYTES (STAGES * STAGE_BYTES)  // 65536

// -------- scratch (device globals; no allocation allowed) --------
__device__ __half g_A[(size_t)B_SZ * D_SZ];    // [4096, 3072] combined, fp16
// g_W fragment-ordered: [nb(32)][wn(4)][t(48)][ks(4)][q(4)][lane(32)][8 halves]
//   -> per (nb,wn): stream s = t*4+ks is contiguous with stride 1024 halves.
__device__ __half g_W[(size_t)FOURH * D_SZ];

// ======================= helpers =======================
__device__ __forceinline__ uint32_t smem_u32(const void* p) {
    uint32_t a;
    asm("{ .reg .u64 t; cvta.to.shared.u64 t, %1; cvt.u32.u64 %0, t; }"
        : "=r"(a) : "l"(p));
    return a;
}

__device__ __forceinline__ void cp16(uint32_t dst, const void* src) {
    asm volatile("cp.async.cg.shared.global [%0], [%1], 16;"
                 :: "r"(dst), "l"(__cvta_generic_to_global(src)));
}
#define CP_COMMIT() asm volatile("cp.async.commit_group;")

__device__ __forceinline__ void ldx4(uint32_t& r0, uint32_t& r1, uint32_t& r2,
                                     uint32_t& r3, uint32_t addr) {
    asm volatile("ldmatrix.sync.aligned.m8n8.x4.shared.b16 {%0,%1,%2,%3}, [%4];"
                 : "=r"(r0), "=r"(r1), "=r"(r2), "=r"(r3) : "r"(addr));
}

__device__ __forceinline__ void mma16816(float* c, const uint32_t* a,
                                         uint32_t b0, uint32_t b1) {
    asm volatile(
        "mma.sync.aligned.m16n8k16.row.col.f32.f16.f16.f32 "
        "{%0,%1,%2,%3}, {%4,%5,%6,%7}, {%8,%9}, {%0,%1,%2,%3};"
        : "+f"(c[0]), "+f"(c[1]), "+f"(c[2]), "+f"(c[3])
        : "r"(a[0]), "r"(a[1]), "r"(a[2]), "r"(a[3]), "r"(b0), "r"(b1));
}

__device__ __forceinline__ float tanh_ap(float x) {
    float y;
    asm("tanh.approx.f32 %0, %1;" : "=f"(y) : "f"(x));
    return y;
}
__device__ __forceinline__ float sigf(float x) {
    return 0.5f * tanh_ap(0.5f * x) + 0.5f;
}

// ======================= merged conversion kernel =======================
#define A_BLK 12288u
#define W_BLK 12288u

__global__ void __launch_bounds__(256)
conv_all_kernel(const float* __restrict__ x, const float* __restrict__ h,
                const float* __restrict__ Wi, const float* __restrict__ Wf,
                const float* __restrict__ Wc, const float* __restrict__ Wo)
{
    const unsigned bid = blockIdx.x;
    if (bid < A_BLK) {
        size_t e = ((size_t)bid * 256 + threadIdx.x) * 4;
        int r = (int)(e / D_SZ), k = (int)(e % D_SZ);
        float4 v = (k < IN_SZ)
            ? *reinterpret_cast<const float4*>(x + (size_t)r * IN_SZ + k)
            : *reinterpret_cast<const float4*>(h + (size_t)r * HID_SZ + (k - IN_SZ));
        __half2 lo = __floats2half2_rn(v.x, v.y);
        __half2 hi = __floats2half2_rn(v.z, v.w);
        uint2 pk;
        pk.x = *reinterpret_cast<uint32_t*>(&lo);
        pk.y = *reinterpret_cast<uint32_t*>(&hi);
        *reinterpret_cast<uint2*>(g_A + e) = pk;
    } else {
        // One 16B chunk per thread; gid = [nb][wn][t][ks][q][lane].
        unsigned gid = (bid - A_BLK) * 256 + threadIdx.x;
        int lane = gid & 31;
        int q    = (gid >> 5) & 3;
        int ks   = (gid >> 7) & 3;
        unsigned rem = gid >> 9;          // [nb][wn][t], 0..6143
        int t  = (int)(rem % 48u);
        unsigned rem2 = rem / 48u;        // 0..127
        int wn = (int)(rem2 & 3u);
        int nb = (int)(rem2 >> 2);

        const int nl = lane >> 2, kk = (lane & 3) * 2;
        const int k0 = t * 64 + ks * 16 + kk;
        __half out8[8];
#pragma unroll
        for (int i = 0; i < 2; i++) {
            int nf = 2 * q + i;           // n8 tile index within warp's 64 cols
            int hp = nf >> 2, g = nf & 3; // hp: hidden-col half, g: gate
            int hr = nb * 64 + wn * 16 + hp * 8 + nl;
            const float* W = (g == 0) ? Wi : (g == 1) ? Wf : (g == 2) ? Wc : Wo;
            float2 lo = *reinterpret_cast<const float2*>(W + (size_t)hr * D_SZ + k0);
            float2 hi = *reinterpret_cast<const float2*>(W + (size_t)hr * D_SZ + k0 + 8);
            out8[i * 4 + 0] = __float2half_rn(lo.x);
            out8[i * 4 + 1] = __float2half_rn(lo.y);
            out8[i * 4 + 2] = __float2half_rn(hi.x);
            out8[i * 4 + 3] = __float2half_rn(hi.y);
        }
        *reinterpret_cast<uint4*>(g_W + (size_t)gid * 8) =
            *reinterpret_cast<uint4*>(out8);
    }
}

// ======================= main fused GEMM + LSTM epilogue =======================
// 256 threads, warp grid 2 (M) x 4 (N), warp tile 64x64.
// A via cp.async->smem->ldmatrix; B via direct fragment-ordered LDG.128 with a
// distance-2, 4-slot register ring (slot == ks, all indices static).
__global__ void __launch_bounds__(256, 1)
lstm_gemm_kernel(const float* __restrict__ c_prev,
                 const float* __restrict__ b_i, const float* __restrict__ b_f,
                 const float* __restrict__ b_c, const float* __restrict__ b_o,
                 float* __restrict__ out)
{
    extern __shared__ __align__(128) char smem[];
    const uint32_t sb = smem_u32(smem);
    const int tid = threadIdx.x;
    const int wid = tid >> 5, lane = tid & 31;
    const int wm = wid >> 2;            // 0..1  (M warp, 64 rows)
    const int wn = wid & 3;             // 0..3  (N warp, 64 cols)
    const int nb = blockIdx.x;          // 0..31
    const int m0 = blockIdx.y << 7;     // row block of 128

    const __half* gA = g_A + (size_t)m0 * D_SZ;
    // B fragment stream base for this (nb, wn, lane):
    //   halves: nb*786432 + wn*196608 + lane*8 ; stream stride 1024 halves = 128 uint4
    const uint4* Bp = reinterpret_cast<const uint4*>(
        g_W + (size_t)nb * 786432 + (size_t)wn * 196608 + (size_t)lane * 8);

    // ---- cp.async A loader: 256 threads, 4 chunks each ----
    const int ldrow = tid >> 1;          // 0..127
    const int ldc0  = (tid & 1) * 4;     // chunk 0..3 or 4..7
    auto load_stage = [&](int s, int kt) {
        uint32_t base = sb + (uint32_t)s * STAGE_BYTES;
        const __half* srcA = gA + (size_t)ldrow * D_SZ + kt * BK + ldc0 * 8;
#pragma unroll
        for (int i = 0; i < 4; i++) {
            uint32_t off = (uint32_t)(ldrow << 7) + (uint32_t)((ldc0 + i) << 4);
            uint32_t so = off ^ (((uint32_t)ldrow & 7) << 4);
            cp16(base + so, srcA + i * 8);
        }
    };

    // ---- A ldmatrix addressing ----
    const int laneRow = lane & 15;
    const uint32_t laneK = (uint32_t)(lane >> 4) << 4;
    const uint32_t swzm = ((uint32_t)laneRow & 7) << 4;
    uint32_t rowA[4];
#pragma unroll
    for (int f = 0; f < 4; f++)
        rowA[f] = (uint32_t)((wm * 64 + f * 16 + laneRow) << 7);
    uint32_t colxs[4];
#pragma unroll
    for (int ks = 0; ks < 4; ks++)
        colxs[ks] = (((uint32_t)ks << 5) | laneK) ^ swzm;

    float acc[4][8][4];
#pragma unroll
    for (int i = 0; i < 4; i++)
#pragma unroll
        for (int j = 0; j < 8; j++)
#pragma unroll
            for (int r = 0; r < 4; r++) acc[i][j][r] = 0.f;

    // ---- B register ring: 4 slots x 16 regs ----
    uint32_t bb[4][16];
    auto load_b = [&](int slot, int s) {
        const uint4* p = Bp + (size_t)s * 128;
#pragma unroll
        for (int q = 0; q < 4; q++) {
            uint4 v = p[q * 32];
            bb[slot][4 * q + 0] = v.x;
            bb[slot][4 * q + 1] = v.y;
            bb[slot][4 * q + 2] = v.z;
            bb[slot][4 * q + 3] = v.w;
        }
    };

    // ---- prologue ----
    load_stage(0, 0); CP_COMMIT();
    load_stage(1, 1); CP_COMMIT();
    load_stage(2, 2); CP_COMMIT();
    load_b(0, 0);
    load_b(1, 1);

#pragma unroll 1
    for (int t = 0; t < NTILES; t++) {
        if (t >= NTILES - 3) asm volatile("cp.async.wait_group 0;" ::: "memory");
        else                 asm volatile("cp.async.wait_group 2;" ::: "memory");
        __syncthreads();

        if (t + 3 < NTILES) {
            load_stage((t + 3) % STAGES, t + 3);
            CP_COMMIT();
        }

        const uint32_t stage = sb + (uint32_t)(t % STAGES) * STAGE_BYTES;
#pragma unroll
        for (int ks = 0; ks < 4; ks++) {
            const int s2 = t * 4 + ks + 2;
            if (s2 < NSTREAM) load_b((ks + 2) & 3, s2);   // distance-2 prefetch

            uint32_t a[4][4];
#pragma unroll
            for (int mf = 0; mf < 4; mf++)
                ldx4(a[mf][0], a[mf][1], a[mf][2], a[mf][3],
                     stage + rowA[mf] + colxs[ks]);

#pragma unroll
            for (int mf = 0; mf < 4; mf++)
#pragma unroll
                for (int nf = 0; nf < 8; nf++) {
                    const int bi = 4 * (nf >> 1) + 2 * (nf & 1);
                    mma16816(acc[mf][nf], a[mf], bb[ks][bi], bb[ks][bi + 1]);
                }
        }
    }

    // ---- fused LSTM epilogue (all in registers) ----
    // nf = hp*4 + gate; thread owns cols hp*8 + 2*(lane&3) + {0,1} per hp.
    const int l2 = lane & 3;
    const int nl = lane >> 2;
    float bia[2][4][2];
#pragma unroll
    for (int hp = 0; hp < 2; hp++) {
        const int hc = nb * 64 + wn * 16 + hp * 8 + 2 * l2;
        const float2 v0 = *reinterpret_cast<const float2*>(b_i + hc);
        const float2 v1 = *reinterpret_cast<const float2*>(b_f + hc);
        const float2 v2 = *reinterpret_cast<const float2*>(b_c + hc);
        const float2 v3 = *reinterpret_cast<const float2*>(b_o + hc);
        bia[hp][0][0] = v0.x; bia[hp][0][1] = v0.y;
        bia[hp][1][0] = v1.x; bia[hp][1][1] = v1.y;
        bia[hp][2][0] = v2.x; bia[hp][2][1] = v2.y;
        bia[hp][3][0] = v3.x; bia[hp][3][1] = v3.y;
    }

#pragma unroll
    for (int mf = 0; mf < 4; mf++) {
#pragma unroll
        for (int rh = 0; rh < 2; rh++) {
            const int m = m0 + wm * 64 + mf * 16 + nl + rh * 8;
#pragma unroll
            for (int hp = 0; hp < 2; hp++) {
                const int hc = nb * 64 + wn * 16 + hp * 8 + 2 * l2;
                const float2 cp2 = *reinterpret_cast<const float2*>(
                    c_prev + (size_t)m * HID_SZ + hc);
                const float cpv[2] = {cp2.x, cp2.y};
                float hv[2], cv[2];
#pragma unroll
                for (int p = 0; p < 2; p++) {
                    const int ci = rh * 2 + p;
                    float gi = acc[mf][hp * 4 + 0][ci] + bia[hp][0][p];
                    float gf = acc[mf][hp * 4 + 1][ci] + bia[hp][1][p];
                    float gc = acc[mf][hp * 4 + 2][ci] + bia[hp][2][p];
                    float go = acc[mf][hp * 4 + 3][ci] + bia[hp][3][p];
                    float it = sigf(gi);
                    float ft = sigf(gf);
                    float gt = tanh_ap(gc);
                    float ot = sigf(go);
                    float ct = ft * cpv[p] + it * gt;
                    cv[p] = ct;
                    hv[p] = ot * tanh_ap(ct);
                }
                float2 h2 = {hv[0], hv[1]};
                float2 c2 = {cv[0], cv[1]};
                *reinterpret_cast<float2*>(out + (size_t)m * HID_SZ + hc) = h2;
                *reinterpret_cast<float2*>(out + (size_t)B_SZ * HID_SZ +
                                           (size_t)m * HID_SZ + hc) = c2;
            }
        }
    }
}

// ======================= launcher =======================
extern "C" void kernel_launch(void* const* d_in, const int* in_sizes, int n_in,
                              void* d_out, int out_size) {
    const float* x  = (const float*)d_in[0];
    const float* h  = (const float*)d_in[1];
    const float* c  = (const float*)d_in[2];
    const float* Wi = (const float*)d_in[3];
    const float* bi = (const float*)d_in[4];
    const float* Wf = (const float*)d_in[5];
    const float* bf = (const float*)d_in[6];
    const float* Wc = (const float*)d_in[7];
    const float* bc = (const float*)d_in[8];
    const float* Wo = (const float*)d_in[9];
    const float* bo = (const float*)d_in[10];
    float* out = (float*)d_out;

    cudaFuncSetAttribute(lstm_gemm_kernel,
                         cudaFuncAttributeMaxDynamicSharedMemorySize, SMEM_BYTES);

    conv_all_kernel<<<A_BLK + W_BLK, 256>>>(x, h, Wi, Wf, Wc, Wo);
    lstm_gemm_kernel<<<dim3(HID_SZ / 64, B_SZ / TM), 256, SMEM_BYTES>>>(
        c, bi, bf, bc, bo, out);
}